// round 10
// baseline (speedup 1.0000x reference)
#include <cuda_runtime.h>
#include <math.h>

#define NQ 4
#define NL 3
#define NG (NL * NQ)

// ---------------------------------------------------------------------------
// Batch-invariant data written by prep kernel.
// For g < 8 (layers 0,1): g_rotp[g*8+k] = Rot entries dup-packed {v,v}:
//   r00.r, r00.i, r01.r, r01.i, r10.r, r10.i, r11.r, r11.i
// For g >= 8 (last layer, RZ(om) dropped — diagonal before measurement):
//   ct, st, -st, -ct, cos(phi), sin(phi), -sin(phi), 0   (dup-packed)
// g_scaleh[g] = scaling[l,q] * pi * 0.5  (half-angle factor)
// ---------------------------------------------------------------------------
__device__ __align__(16) float2 g_rotp[NG * 8];
__device__ __align__(16) float g_scaleh[NG];

// ---------------------------------------------------------------------------
// Packed f32x2 primitives (Blackwell FFMA2 path — PTX-only, ptxas won't emit)
// ---------------------------------------------------------------------------
typedef unsigned long long f2;

__device__ __forceinline__ f2 pack2(float lo, float hi) {
    f2 r; asm("mov.b64 %0, {%1, %2};" : "=l"(r) : "f"(lo), "f"(hi)); return r;
}
__device__ __forceinline__ void unpack2(f2 v, float& lo, float& hi) {
    asm("mov.b64 {%0, %1}, %2;" : "=f"(lo), "=f"(hi) : "l"(v));
}
__device__ __forceinline__ f2 fma2(f2 a, f2 b, f2 c) {
    f2 d; asm("fma.rn.f32x2 %0, %1, %2, %3;" : "=l"(d) : "l"(a), "l"(b), "l"(c)); return d;
}
__device__ __forceinline__ f2 mul2(f2 a, f2 b) {
    f2 d; asm("mul.rn.f32x2 %0, %1, %2;" : "=l"(d) : "l"(a), "l"(b)); return d;
}
__device__ __forceinline__ f2 add2(f2 a, f2 b) {
    f2 d; asm("add.rn.f32x2 %0, %1, %2;" : "=l"(d) : "l"(a), "l"(b)); return d;
}
// Sign-bit flip on ALU pipe (2x LOP3) — offloads the saturated FMA pipe.
__device__ __forceinline__ f2 neg2(f2 v) {
    return v ^ 0x8000000080000000ULL;
}

struct Cp { f2 r, i; };  // packed complex: lane0 = sample A, lane1 = sample B

// (a*b) complex, packed; negation on alu pipe
__device__ __forceinline__ Cp cmulp(Cp a, Cp b) {
    Cp o;
    f2 t = mul2(a.i, b.i);
    o.r = fma2(a.r, b.r, neg2(t));
    o.i = fma2(a.i, b.r, mul2(a.r, b.i));
    return o;
}

__device__ __forceinline__ float fast_tanh(float v) {
    float e = __expf(2.0f * v);
    return 1.0f - __fdividef(2.0f, e + 1.0f);
}

// ---------------------------------------------------------------------------
// Prep kernel
// ---------------------------------------------------------------------------
__global__ void prep_kernel(const float* __restrict__ w, const float* __restrict__ sc) {
    int g = threadIdx.x;
    if (g < NG) {
        float phi = w[3 * g + 0];
        float th  = w[3 * g + 1];
        float om  = w[3 * g + 2];
        float e[8];
        if (g < 2 * NQ) {
            // Full Rot(phi, theta, omega) = RZ(om) RY(th) RZ(phi)
            float ct, st, cp, sp, cm, sm;
            sincosf(0.5f * th, &st, &ct);
            sincosf(0.5f * (phi + om), &sp, &cp);
            sincosf(0.5f * (phi - om), &sm, &cm);
            e[0] =  ct * cp;  e[1] = -ct * sp;   // r00
            e[2] = -st * cm;  e[3] = -st * sm;   // r01
            e[4] =  st * cm;  e[5] = -st * sm;   // r10
            e[6] =  ct * cp;  e[7] =  ct * sp;   // r11
        } else {
            // Last layer: RZ(om) dropped (diag before measurement, CNOTs keep
            // it diagonal, |amp|^2 invariant). Store RY(th) + e^{i phi}.
            float ct, st, er, ei;
            sincosf(0.5f * th, &st, &ct);
            sincosf(phi, &ei, &er);
            e[0] = ct; e[1] = st; e[2] = -st; e[3] = -ct;
            e[4] = er; e[5] = ei; e[6] = -ei; e[7] = 0.0f;
        }
#pragma unroll
        for (int k = 0; k < 8; k++) g_rotp[g * 8 + k] = make_float2(e[k], e[k]);
        g_scaleh[g] = sc[g] * (3.14159265358979323846f * 0.5f);
    }
}

// Per-gate matrix in registers (4 x LDG.128), prefetchable.
struct GM { ulonglong2 e0, e1, e2, e3; };

__device__ __forceinline__ GM load_gm(int g) {
    const ulonglong2* rp = reinterpret_cast<const ulonglong2*>(g_rotp) + g * 4;
    GM m; m.e0 = rp[0]; m.e1 = rp[1]; m.e2 = rp[2]; m.e3 = rp[3];
    return m;
}

// ---------------------------------------------------------------------------
// Fused gate up to GLOBAL PHASE (layers 0..NL-2):
//   U' = Rot @ diag(1, p) @ RY(ang),  p = e^{i ang/2} = (ch, sh)
// ---------------------------------------------------------------------------
__device__ __forceinline__ void build_u_p(const GM& m, float tA, float tB, float sH,
                                          Cp& u00, Cp& u01, Cp& u10, Cp& u11) {
    float sA, cA, sB, cB;
    __sincosf(tA * sH, &sA, &cA);
    __sincosf(tB * sH, &sB, &cB);
    f2 sh = pack2(sA, sB), ch = pack2(cA, cB);
    f2 nsh = neg2(sh);

    Cp r00 = {m.e0.x, m.e0.y}, r01 = {m.e1.x, m.e1.y};
    Cp r10 = {m.e2.x, m.e2.y}, r11 = {m.e3.x, m.e3.y};

    // D col1 = Rot col1 * p
    Cp d01, d11;
    d01.r = fma2(r01.i, nsh, mul2(r01.r, ch));
    d01.i = fma2(r01.i, ch,  mul2(r01.r, sh));
    d11.r = fma2(r11.i, nsh, mul2(r11.r, ch));
    d11.i = fma2(r11.i, ch,  mul2(r11.r, sh));

    // U = [ (r00, d01) ; (r10, d11) ] @ [[ch, -sh], [sh, ch]]
    u00.r = fma2(sh, d01.r, mul2(ch, r00.r));
    u00.i = fma2(sh, d01.i, mul2(ch, r00.i));
    u01.r = fma2(nsh, r00.r, mul2(ch, d01.r));
    u01.i = fma2(nsh, r00.i, mul2(ch, d01.i));
    u10.r = fma2(sh, d11.r, mul2(ch, r10.r));
    u10.i = fma2(sh, d11.i, mul2(ch, r10.i));
    u11.r = fma2(nsh, r10.r, mul2(ch, d11.r));
    u11.i = fma2(nsh, r10.i, mul2(ch, d11.i));
}

// Last-layer gate (RZ(om) dropped): U = RY(th) @ diag(1, pp) @ RY(ang),
// pp = e^{i(phi + ang/2)}.
__device__ __forceinline__ void build_u_last(const GM& m, float tA, float tB, float sH,
                                             Cp& u00, Cp& u01, Cp& u10, Cp& u11) {
    float sA, cA, sB, cB;
    __sincosf(tA * sH, &sA, &cA);
    __sincosf(tB * sH, &sB, &cB);
    f2 sh = pack2(sA, sB), ch = pack2(cA, cB);

    f2 ct = m.e0.x, st = m.e0.y, nst = m.e1.x, nct = m.e1.y;
    f2 er = m.e2.x, ei = m.e2.y, nei = m.e3.x;

    f2 ppr = fma2(nei, sh, mul2(er, ch));   // cos(phi + a/2)
    f2 ppi = fma2(ei,  ch, mul2(er, sh));   // sin(phi + a/2)

    f2 A  = mul2(ct,  ch);   // ct·ch
    f2 Bp = mul2(nst, sh);   // -st·sh
    f2 C  = mul2(ct,  sh);   // ct·sh
    f2 nC = mul2(nct, sh);   // -ct·sh
    f2 D  = mul2(st,  ch);   // st·ch
    f2 nD = mul2(nst, ch);   // -st·ch

    u00.r = fma2(Bp, ppr, A);  u00.i = mul2(Bp, ppi);
    u01.r = fma2(nD, ppr, nC); u01.i = mul2(nD, ppi);
    u10.r = fma2(C,  ppr, D);  u10.i = mul2(C,  ppi);
    u11.r = fma2(A,  ppr, Bp); u11.i = mul2(A,  ppi);
}

// Column-0-only variant for layer 0 (state |0000>).
__device__ __forceinline__ void build_u_col0(const GM& m, float tA, float tB, float sH,
                                             Cp& u00, Cp& u10) {
    float sA, cA, sB, cB;
    __sincosf(tA * sH, &sA, &cA);
    __sincosf(tB * sH, &sB, &cB);
    f2 sh = pack2(sA, sB), ch = pack2(cA, cB);
    f2 nsh = neg2(sh);

    Cp r00 = {m.e0.x, m.e0.y}, r01 = {m.e1.x, m.e1.y};
    Cp r10 = {m.e2.x, m.e2.y}, r11 = {m.e3.x, m.e3.y};

    Cp d01, d11;
    d01.r = fma2(r01.i, nsh, mul2(r01.r, ch));
    d01.i = fma2(r01.i, ch,  mul2(r01.r, sh));
    d11.r = fma2(r11.i, nsh, mul2(r11.r, ch));
    d11.i = fma2(r11.i, ch,  mul2(r11.r, sh));

    u00.r = fma2(sh, d01.r, mul2(ch, r00.r));
    u00.i = fma2(sh, d01.i, mul2(ch, r00.i));
    u10.r = fma2(sh, d11.r, mul2(ch, r10.r));
    u10.i = fma2(sh, d11.i, mul2(ch, r10.i));
}

// Amplitude index: i = b0*8 + b1*4 + b2*2 + b3 (qubit q -> mask 8>>q).
// Imag negations moved to ALU pipe via neg2.
template <int M>
__device__ __forceinline__ void apply_gate_p(Cp* s, Cp u00, Cp u01, Cp u10, Cp u11) {
    f2 n00 = neg2(u00.i), n01 = neg2(u01.i);
    f2 n10 = neg2(u10.i), n11 = neg2(u11.i);
#pragma unroll
    for (int i = 0; i < 16; i++) {
        if ((i & M) == 0) {
            Cp a0 = s[i], a1 = s[i | M];
            f2 r0 = mul2(u00.r, a0.r); r0 = fma2(n00, a0.i, r0);
            r0 = fma2(u01.r, a1.r, r0); r0 = fma2(n01, a1.i, r0);
            f2 i0 = mul2(u00.r, a0.i); i0 = fma2(u00.i, a0.r, i0);
            i0 = fma2(u01.r, a1.i, i0); i0 = fma2(u01.i, a1.r, i0);
            f2 r1 = mul2(u10.r, a0.r); r1 = fma2(n10, a0.i, r1);
            r1 = fma2(u11.r, a1.r, r1); r1 = fma2(n11, a1.i, r1);
            f2 i1 = mul2(u10.r, a0.i); i1 = fma2(u10.i, a0.r, i1);
            i1 = fma2(u11.r, a1.i, i1); i1 = fma2(u11.i, a1.r, i1);
            s[i].r = r0; s[i].i = i0;
            s[i | M].r = r1; s[i | M].i = i1;
        }
    }
}

template <int MC, int MT>
__device__ __forceinline__ void cnotp(Cp* s) {
#pragma unroll
    for (int i = 0; i < 16; i++) {
        if ((i & MC) && !(i & MT)) {
            Cp tmp = s[i]; s[i] = s[i | MT]; s[i | MT] = tmp;
        }
    }
}

__device__ __forceinline__ void cnot_ring_p(Cp* s) {
    cnotp<8, 4>(s);
    cnotp<4, 2>(s);
    cnotp<2, 1>(s);
    cnotp<1, 8>(s);
}

__global__ __launch_bounds__(128)
void qsim_kernel(const float* __restrict__ x, float* __restrict__ out, int B2) {
    int t = blockIdx.x * blockDim.x + threadIdx.x;
    if (t >= B2) return;

    const f2 M2 = pack2(-2.0f, -2.0f);

    // Hoist all 12 half-angle scale factors as 3 vector loads.
    const float4* scp = reinterpret_cast<const float4*>(g_scaleh);
    float4 sc0 = scp[0], sc1 = scp[1], sc2 = scp[2];

    const float4* x4 = reinterpret_cast<const float4*>(x);
    float4 xa = x4[2 * t], xb = x4[2 * t + 1];
    float tqA[NQ] = {fast_tanh(xa.x), fast_tanh(xa.y), fast_tanh(xa.z), fast_tanh(xa.w)};
    float tqB[NQ] = {fast_tanh(xb.x), fast_tanh(xb.y), fast_tanh(xb.z), fast_tanh(xb.w)};

    Cp s[16];

    // ---- Layer 0: |0000> -> product state from column 0 of each U, then ring
    {
        // Batch the 4 matrix loads up front (MLP), then build.
        GM m0 = load_gm(0), m1 = load_gm(1), m2 = load_gm(2), m3 = load_gm(3);
        Cp c0[NQ], c1[NQ];
        build_u_col0(m0, tqA[0], tqB[0], sc0.x, c0[0], c1[0]);
        build_u_col0(m1, tqA[1], tqB[1], sc0.y, c0[1], c1[1]);
        build_u_col0(m2, tqA[2], tqB[2], sc0.z, c0[2], c1[2]);
        build_u_col0(m3, tqA[3], tqB[3], sc0.w, c0[3], c1[3]);

        Cp t01[4], t23[4];
        t01[0] = cmulp(c0[0], c0[1]); t01[1] = cmulp(c0[0], c1[1]);
        t01[2] = cmulp(c1[0], c0[1]); t01[3] = cmulp(c1[0], c1[1]);
        t23[0] = cmulp(c0[2], c0[3]); t23[1] = cmulp(c0[2], c1[3]);
        t23[2] = cmulp(c1[2], c0[3]); t23[3] = cmulp(c1[2], c1[3]);
#pragma unroll
        for (int i = 0; i < 16; i++) s[i] = cmulp(t01[i >> 2], t23[i & 3]);
        cnot_ring_p(s);
    }

    // ---- Layer 1: generic fused gates, next-gate matrix prefetched
    {
        GM m = load_gm(4);
        Cp u00, u01, u10, u11;
        {
            GM mn = load_gm(5);
            build_u_p(m, tqA[0], tqB[0], sc1.x, u00, u01, u10, u11);
            apply_gate_p<8>(s, u00, u01, u10, u11);
            m = mn;
        }
        {
            GM mn = load_gm(6);
            build_u_p(m, tqA[1], tqB[1], sc1.y, u00, u01, u10, u11);
            apply_gate_p<4>(s, u00, u01, u10, u11);
            m = mn;
        }
        {
            GM mn = load_gm(7);
            build_u_p(m, tqA[2], tqB[2], sc1.z, u00, u01, u10, u11);
            apply_gate_p<2>(s, u00, u01, u10, u11);
            m = mn;
        }
        build_u_p(m, tqA[3], tqB[3], sc1.w, u00, u01, u10, u11);
        apply_gate_p<1>(s, u00, u01, u10, u11);
        cnot_ring_p(s);
    }

    // ---- Layer 2 (last): RZ(om) dropped, cheap build, prefetched
    {
        GM m = load_gm(8);
        Cp u00, u01, u10, u11;
        {
            GM mn = load_gm(9);
            build_u_last(m, tqA[0], tqB[0], sc2.x, u00, u01, u10, u11);
            apply_gate_p<8>(s, u00, u01, u10, u11);
            m = mn;
        }
        {
            GM mn = load_gm(10);
            build_u_last(m, tqA[1], tqB[1], sc2.y, u00, u01, u10, u11);
            apply_gate_p<4>(s, u00, u01, u10, u11);
            m = mn;
        }
        {
            GM mn = load_gm(11);
            build_u_last(m, tqA[2], tqB[2], sc2.z, u00, u01, u10, u11);
            apply_gate_p<2>(s, u00, u01, u10, u11);
            m = mn;
        }
        build_u_last(m, tqA[3], tqB[3], sc2.w, u00, u01, u10, u11);
        apply_gate_p<1>(s, u00, u01, u10, u11);
        cnot_ring_p(s);
    }

    // ---- Probabilities and <Z_w>, shared partial sums
    f2 p[16];
#pragma unroll
    for (int i = 0; i < 16; i++) p[i] = fma2(s[i].r, s[i].r, mul2(s[i].i, s[i].i));

    f2 a[8], bb[4], c[2];
#pragma unroll
    for (int k = 0; k < 8; k++) a[k] = add2(p[2 * k], p[2 * k + 1]);
#pragma unroll
    for (int k = 0; k < 4; k++) bb[k] = add2(a[2 * k], a[2 * k + 1]);
    c[0] = add2(bb[0], bb[1]); c[1] = add2(bb[2], bb[3]);
    f2 tot = add2(c[0], c[1]);

    // z_w = tot - 2 * (sum of p where bit_w set)
    f2 s0 = c[1];                                            // mask 8
    f2 s1 = add2(bb[1], bb[3]);                              // mask 4
    f2 s2 = add2(add2(a[1], a[3]), add2(a[5], a[7]));        // mask 2
    f2 s3 = add2(add2(add2(p[1], p[3]), add2(p[5], p[7])),
                 add2(add2(p[9], p[11]), add2(p[13], p[15])));   // mask 1
    f2 z0 = fma2(M2, s0, tot);
    f2 z1 = fma2(M2, s1, tot);
    f2 z2 = fma2(M2, s2, tot);
    f2 z3 = fma2(M2, s3, tot);

    float z0A, z0B, z1A, z1B, z2A, z2B, z3A, z3B;
    unpack2(z0, z0A, z0B); unpack2(z1, z1A, z1B);
    unpack2(z2, z2A, z2B); unpack2(z3, z3A, z3B);

    float4* o4 = reinterpret_cast<float4*>(out);
    o4[2 * t]     = make_float4(z0A, z1A, z2A, z3A);
    o4[2 * t + 1] = make_float4(z0B, z1B, z2B, z3B);
}

extern "C" void kernel_launch(void* const* d_in, const int* in_sizes, int n_in,
                              void* d_out, int out_size) {
    const float* x  = (const float*)d_in[0];   // [B, 4]
    const float* w  = (const float*)d_in[1];   // [3, 4, 3]
    const float* sc = (const float*)d_in[2];   // [3, 4]
    float* out = (float*)d_out;                // [B, 4]
    int B = in_sizes[0] / NQ;
    int B2 = B / 2;                            // 2 samples per thread

    prep_kernel<<<1, 32>>>(w, sc);
    int threads = 128;
    int blocks = (B2 + threads - 1) / threads;
    qsim_kernel<<<blocks, threads>>>(x, out, B2);
}

// round 13
// speedup vs baseline: 1.0306x; 1.0306x over previous
#include <cuda_runtime.h>
#include <math.h>

#define NQ 4
#define NL 3
#define NG (NL * NQ)

// ---------------------------------------------------------------------------
// Packed f32x2 primitives (Blackwell FFMA2 path — PTX-only, ptxas won't emit)
// ---------------------------------------------------------------------------
typedef unsigned long long f2;

__device__ __forceinline__ f2 pack2(float lo, float hi) {
    f2 r; asm("mov.b64 %0, {%1, %2};" : "=l"(r) : "f"(lo), "f"(hi)); return r;
}
__device__ __forceinline__ void unpack2(f2 v, float& lo, float& hi) {
    asm("mov.b64 {%0, %1}, %2;" : "=f"(lo), "=f"(hi) : "l"(v));
}
__device__ __forceinline__ f2 fma2(f2 a, f2 b, f2 c) {
    f2 d; asm("fma.rn.f32x2 %0, %1, %2, %3;" : "=l"(d) : "l"(a), "l"(b), "l"(c)); return d;
}
__device__ __forceinline__ f2 mul2(f2 a, f2 b) {
    f2 d; asm("mul.rn.f32x2 %0, %1, %2;" : "=l"(d) : "l"(a), "l"(b)); return d;
}
__device__ __forceinline__ f2 add2(f2 a, f2 b) {
    f2 d; asm("add.rn.f32x2 %0, %1, %2;" : "=l"(d) : "l"(a), "l"(b)); return d;
}
// Sign-bit flip on ALU pipe (2x LOP3) — offloads the FMA pipe.
__device__ __forceinline__ f2 neg2(f2 v) {
    return v ^ 0x8000000080000000ULL;
}

struct Cp { f2 r, i; };  // packed complex: lane0 = sample A, lane1 = sample B

// (a*b) complex, packed; negation on alu pipe
__device__ __forceinline__ Cp cmulp(Cp a, Cp b) {
    Cp o;
    f2 t = mul2(a.i, b.i);
    o.r = fma2(a.r, b.r, neg2(t));
    o.i = fma2(a.i, b.r, mul2(a.r, b.i));
    return o;
}

__device__ __forceinline__ float fast_tanh(float v) {
    float e = __expf(2.0f * v);
    return 1.0f - __fdividef(2.0f, e + 1.0f);
}

// Per-gate matrix in registers (4 x LDS.128).
struct GM { ulonglong2 e0, e1, e2, e3; };

__device__ __forceinline__ GM load_gm(const float2* sm_rot, int g) {
    const ulonglong2* rp = reinterpret_cast<const ulonglong2*>(sm_rot) + g * 4;
    GM m; m.e0 = rp[0]; m.e1 = rp[1]; m.e2 = rp[2]; m.e3 = rp[3];
    return m;
}

// ---------------------------------------------------------------------------
// Fused gate up to GLOBAL PHASE (layers 0..NL-2):
//   U' = Rot @ diag(1, p) @ RY(ang),  p = e^{i ang/2} = (ch, sh)
// ---------------------------------------------------------------------------
__device__ __forceinline__ void build_u_p(const GM& m, float tA, float tB, float sH,
                                          Cp& u00, Cp& u01, Cp& u10, Cp& u11) {
    float sA, cA, sB, cB;
    __sincosf(tA * sH, &sA, &cA);
    __sincosf(tB * sH, &sB, &cB);
    f2 sh = pack2(sA, sB), ch = pack2(cA, cB);
    f2 nsh = neg2(sh);

    Cp r00 = {m.e0.x, m.e0.y}, r01 = {m.e1.x, m.e1.y};
    Cp r10 = {m.e2.x, m.e2.y}, r11 = {m.e3.x, m.e3.y};

    // D col1 = Rot col1 * p
    Cp d01, d11;
    d01.r = fma2(r01.i, nsh, mul2(r01.r, ch));
    d01.i = fma2(r01.i, ch,  mul2(r01.r, sh));
    d11.r = fma2(r11.i, nsh, mul2(r11.r, ch));
    d11.i = fma2(r11.i, ch,  mul2(r11.r, sh));

    // U = [ (r00, d01) ; (r10, d11) ] @ [[ch, -sh], [sh, ch]]
    u00.r = fma2(sh, d01.r, mul2(ch, r00.r));
    u00.i = fma2(sh, d01.i, mul2(ch, r00.i));
    u01.r = fma2(nsh, r00.r, mul2(ch, d01.r));
    u01.i = fma2(nsh, r00.i, mul2(ch, d01.i));
    u10.r = fma2(sh, d11.r, mul2(ch, r10.r));
    u10.i = fma2(sh, d11.i, mul2(ch, r10.i));
    u11.r = fma2(nsh, r10.r, mul2(ch, d11.r));
    u11.i = fma2(nsh, r10.i, mul2(ch, d11.i));
}

// Last-layer gate (RZ(om) dropped): U = RY(th) @ diag(1, pp) @ RY(ang),
// pp = e^{i(phi + ang/2)}.
__device__ __forceinline__ void build_u_last(const GM& m, float tA, float tB, float sH,
                                             Cp& u00, Cp& u01, Cp& u10, Cp& u11) {
    float sA, cA, sB, cB;
    __sincosf(tA * sH, &sA, &cA);
    __sincosf(tB * sH, &sB, &cB);
    f2 sh = pack2(sA, sB), ch = pack2(cA, cB);

    f2 ct = m.e0.x, st = m.e0.y, nst = m.e1.x, nct = m.e1.y;
    f2 er = m.e2.x, ei = m.e2.y, nei = m.e3.x;

    f2 ppr = fma2(nei, sh, mul2(er, ch));   // cos(phi + a/2)
    f2 ppi = fma2(ei,  ch, mul2(er, sh));   // sin(phi + a/2)

    f2 A  = mul2(ct,  ch);   // ct·ch
    f2 Bp = mul2(nst, sh);   // -st·sh
    f2 C  = mul2(ct,  sh);   // ct·sh
    f2 nC = mul2(nct, sh);   // -ct·sh
    f2 D  = mul2(st,  ch);   // st·ch
    f2 nD = mul2(nst, ch);   // -st·ch

    u00.r = fma2(Bp, ppr, A);  u00.i = mul2(Bp, ppi);
    u01.r = fma2(nD, ppr, nC); u01.i = mul2(nD, ppi);
    u10.r = fma2(C,  ppr, D);  u10.i = mul2(C,  ppi);
    u11.r = fma2(A,  ppr, Bp); u11.i = mul2(A,  ppi);
}

// Column-0-only variant for layer 0 (state |0000>).
__device__ __forceinline__ void build_u_col0(const GM& m, float tA, float tB, float sH,
                                             Cp& u00, Cp& u10) {
    float sA, cA, sB, cB;
    __sincosf(tA * sH, &sA, &cA);
    __sincosf(tB * sH, &sB, &cB);
    f2 sh = pack2(sA, sB), ch = pack2(cA, cB);
    f2 nsh = neg2(sh);

    Cp r00 = {m.e0.x, m.e0.y}, r01 = {m.e1.x, m.e1.y};
    Cp r10 = {m.e2.x, m.e2.y}, r11 = {m.e3.x, m.e3.y};

    Cp d01, d11;
    d01.r = fma2(r01.i, nsh, mul2(r01.r, ch));
    d01.i = fma2(r01.i, ch,  mul2(r01.r, sh));
    d11.r = fma2(r11.i, nsh, mul2(r11.r, ch));
    d11.i = fma2(r11.i, ch,  mul2(r11.r, sh));

    u00.r = fma2(sh, d01.r, mul2(ch, r00.r));
    u00.i = fma2(sh, d01.i, mul2(ch, r00.i));
    u10.r = fma2(sh, d11.r, mul2(ch, r10.r));
    u10.i = fma2(sh, d11.i, mul2(ch, r10.i));
}

// Amplitude index: i = b0*8 + b1*4 + b2*2 + b3 (qubit q -> mask 8>>q).
// Imag negations on ALU pipe via neg2.
template <int M>
__device__ __forceinline__ void apply_gate_p(Cp* s, Cp u00, Cp u01, Cp u10, Cp u11) {
    f2 n00 = neg2(u00.i), n01 = neg2(u01.i);
    f2 n10 = neg2(u10.i), n11 = neg2(u11.i);
#pragma unroll
    for (int i = 0; i < 16; i++) {
        if ((i & M) == 0) {
            Cp a0 = s[i], a1 = s[i | M];
            f2 r0 = mul2(u00.r, a0.r); r0 = fma2(n00, a0.i, r0);
            r0 = fma2(u01.r, a1.r, r0); r0 = fma2(n01, a1.i, r0);
            f2 i0 = mul2(u00.r, a0.i); i0 = fma2(u00.i, a0.r, i0);
            i0 = fma2(u01.r, a1.i, i0); i0 = fma2(u01.i, a1.r, i0);
            f2 r1 = mul2(u10.r, a0.r); r1 = fma2(n10, a0.i, r1);
            r1 = fma2(u11.r, a1.r, r1); r1 = fma2(n11, a1.i, r1);
            f2 i1 = mul2(u10.r, a0.i); i1 = fma2(u10.i, a0.r, i1);
            i1 = fma2(u11.r, a1.i, i1); i1 = fma2(u11.i, a1.r, i1);
            s[i].r = r0; s[i].i = i0;
            s[i | M].r = r1; s[i | M].i = i1;
        }
    }
}

template <int MC, int MT>
__device__ __forceinline__ void cnotp(Cp* s) {
#pragma unroll
    for (int i = 0; i < 16; i++) {
        if ((i & MC) && !(i & MT)) {
            Cp tmp = s[i]; s[i] = s[i | MT]; s[i | MT] = tmp;
        }
    }
}

__device__ __forceinline__ void cnot_ring_p(Cp* s) {
    cnotp<8, 4>(s);
    cnotp<4, 2>(s);
    cnotp<2, 1>(s);
    cnotp<1, 8>(s);
}

// ---------------------------------------------------------------------------
// Single fused kernel: per-CTA gate prep into SMEM, then packed simulation.
// ---------------------------------------------------------------------------
__global__ __launch_bounds__(128)
void qsim_kernel(const float* __restrict__ x, const float* __restrict__ w,
                 const float* __restrict__ sc, float* __restrict__ out, int B2) {
    __shared__ __align__(16) float2 sm_rot[NG * 8];
    __shared__ __align__(16) float  sm_scaleh[NG];

    int tid = threadIdx.x;

    // --- Per-CTA prep: 12 threads compute the batch-invariant gate data.
    // For g < 8 (layers 0,1): full Rot entries dup-packed {v,v}.
    // For g >= 8 (last layer, RZ(om) dropped): ct, st, -st, -ct,
    //   cos(phi), sin(phi), -sin(phi), 0 (dup-packed).
    if (tid < NG) {
        int g = tid;
        float phi = w[3 * g + 0];
        float th  = w[3 * g + 1];
        float om  = w[3 * g + 2];
        float e[8];
        if (g < 2 * NQ) {
            float ct, st, cp, sp, cm, sm;
            sincosf(0.5f * th, &st, &ct);
            sincosf(0.5f * (phi + om), &sp, &cp);
            sincosf(0.5f * (phi - om), &sm, &cm);
            e[0] =  ct * cp;  e[1] = -ct * sp;   // r00
            e[2] = -st * cm;  e[3] = -st * sm;   // r01
            e[4] =  st * cm;  e[5] = -st * sm;   // r10
            e[6] =  ct * cp;  e[7] =  ct * sp;   // r11
        } else {
            float ct, st, er, ei;
            sincosf(0.5f * th, &st, &ct);
            sincosf(phi, &ei, &er);
            e[0] = ct; e[1] = st; e[2] = -st; e[3] = -ct;
            e[4] = er; e[5] = ei; e[6] = -ei; e[7] = 0.0f;
        }
#pragma unroll
        for (int k = 0; k < 8; k++) sm_rot[g * 8 + k] = make_float2(e[k], e[k]);
        sm_scaleh[g] = sc[g] * (3.14159265358979323846f * 0.5f);
    }
    __syncthreads();

    int t = blockIdx.x * blockDim.x + tid;
    if (t >= B2) return;

    const f2 M2 = pack2(-2.0f, -2.0f);

    const float4* scp = reinterpret_cast<const float4*>(sm_scaleh);
    float4 sc0 = scp[0], sc1 = scp[1], sc2 = scp[2];

    const float4* x4 = reinterpret_cast<const float4*>(x);
    float4 xa = x4[2 * t], xb = x4[2 * t + 1];
    float tqA[NQ] = {fast_tanh(xa.x), fast_tanh(xa.y), fast_tanh(xa.z), fast_tanh(xa.w)};
    float tqB[NQ] = {fast_tanh(xb.x), fast_tanh(xb.y), fast_tanh(xb.z), fast_tanh(xb.w)};

    Cp s[16];

    // ---- Layer 0: |0000> -> product state from column 0 of each U, then ring
    {
        GM m0 = load_gm(sm_rot, 0), m1 = load_gm(sm_rot, 1);
        GM m2 = load_gm(sm_rot, 2), m3 = load_gm(sm_rot, 3);
        Cp c0[NQ], c1[NQ];
        build_u_col0(m0, tqA[0], tqB[0], sc0.x, c0[0], c1[0]);
        build_u_col0(m1, tqA[1], tqB[1], sc0.y, c0[1], c1[1]);
        build_u_col0(m2, tqA[2], tqB[2], sc0.z, c0[2], c1[2]);
        build_u_col0(m3, tqA[3], tqB[3], sc0.w, c0[3], c1[3]);

        Cp t01[4], t23[4];
        t01[0] = cmulp(c0[0], c0[1]); t01[1] = cmulp(c0[0], c1[1]);
        t01[2] = cmulp(c1[0], c0[1]); t01[3] = cmulp(c1[0], c1[1]);
        t23[0] = cmulp(c0[2], c0[3]); t23[1] = cmulp(c0[2], c1[3]);
        t23[2] = cmulp(c1[2], c0[3]); t23[3] = cmulp(c1[2], c1[3]);
#pragma unroll
        for (int i = 0; i < 16; i++) s[i] = cmulp(t01[i >> 2], t23[i & 3]);
        cnot_ring_p(s);
    }

    // ---- Layer 1: generic fused gates
    {
        Cp u00, u01, u10, u11;
        build_u_p(load_gm(sm_rot, 4), tqA[0], tqB[0], sc1.x, u00, u01, u10, u11);
        apply_gate_p<8>(s, u00, u01, u10, u11);
        build_u_p(load_gm(sm_rot, 5), tqA[1], tqB[1], sc1.y, u00, u01, u10, u11);
        apply_gate_p<4>(s, u00, u01, u10, u11);
        build_u_p(load_gm(sm_rot, 6), tqA[2], tqB[2], sc1.z, u00, u01, u10, u11);
        apply_gate_p<2>(s, u00, u01, u10, u11);
        build_u_p(load_gm(sm_rot, 7), tqA[3], tqB[3], sc1.w, u00, u01, u10, u11);
        apply_gate_p<1>(s, u00, u01, u10, u11);
        cnot_ring_p(s);
    }

    // ---- Layer 2 (last): RZ(om) dropped, cheap build
    {
        Cp u00, u01, u10, u11;
        build_u_last(load_gm(sm_rot, 8), tqA[0], tqB[0], sc2.x, u00, u01, u10, u11);
        apply_gate_p<8>(s, u00, u01, u10, u11);
        build_u_last(load_gm(sm_rot, 9), tqA[1], tqB[1], sc2.y, u00, u01, u10, u11);
        apply_gate_p<4>(s, u00, u01, u10, u11);
        build_u_last(load_gm(sm_rot, 10), tqA[2], tqB[2], sc2.z, u00, u01, u10, u11);
        apply_gate_p<2>(s, u00, u01, u10, u11);
        build_u_last(load_gm(sm_rot, 11), tqA[3], tqB[3], sc2.w, u00, u01, u10, u11);
        apply_gate_p<1>(s, u00, u01, u10, u11);
        cnot_ring_p(s);
    }

    // ---- Probabilities and <Z_w>, shared partial sums
    f2 p[16];
#pragma unroll
    for (int i = 0; i < 16; i++) p[i] = fma2(s[i].r, s[i].r, mul2(s[i].i, s[i].i));

    f2 a[8], bb[4], c[2];
#pragma unroll
    for (int k = 0; k < 8; k++) a[k] = add2(p[2 * k], p[2 * k + 1]);
#pragma unroll
    for (int k = 0; k < 4; k++) bb[k] = add2(a[2 * k], a[2 * k + 1]);
    c[0] = add2(bb[0], bb[1]); c[1] = add2(bb[2], bb[3]);
    f2 tot = add2(c[0], c[1]);

    // z_w = tot - 2 * (sum of p where bit_w set)
    f2 s0 = c[1];                                            // mask 8
    f2 s1 = add2(bb[1], bb[3]);                              // mask 4
    f2 s2 = add2(add2(a[1], a[3]), add2(a[5], a[7]));        // mask 2
    f2 s3 = add2(add2(add2(p[1], p[3]), add2(p[5], p[7])),
                 add2(add2(p[9], p[11]), add2(p[13], p[15])));   // mask 1
    f2 z0 = fma2(M2, s0, tot);
    f2 z1 = fma2(M2, s1, tot);
    f2 z2 = fma2(M2, s2, tot);
    f2 z3 = fma2(M2, s3, tot);

    float z0A, z0B, z1A, z1B, z2A, z2B, z3A, z3B;
    unpack2(z0, z0A, z0B); unpack2(z1, z1A, z1B);
    unpack2(z2, z2A, z2B); unpack2(z3, z3A, z3B);

    float4* o4 = reinterpret_cast<float4*>(out);
    o4[2 * t]     = make_float4(z0A, z1A, z2A, z3A);
    o4[2 * t + 1] = make_float4(z0B, z1B, z2B, z3B);
}

extern "C" void kernel_launch(void* const* d_in, const int* in_sizes, int n_in,
                              void* d_out, int out_size) {
    const float* x  = (const float*)d_in[0];   // [B, 4]
    const float* w  = (const float*)d_in[1];   // [3, 4, 3]
    const float* sc = (const float*)d_in[2];   // [3, 4]
    float* out = (float*)d_out;                // [B, 4]
    int B = in_sizes[0] / NQ;
    int B2 = B / 2;                            // 2 samples per thread

    int threads = 128;
    int blocks = (B2 + threads - 1) / threads;
    qsim_kernel<<<blocks, threads>>>(x, w, sc, out, B2);
}